// round 14
// baseline (speedup 1.0000x reference)
#include <cuda_runtime.h>
#include <math.h>
#include <stdint.h>

// Problem constants
#define B_    2
#define N_    2048
#define E_    768
#define H_    12
#define D_    64
#define M_    (B_ * N_)       // 4096
#define QKV_N (3 * E_)        // 2304

// Scratch (device globals — allocation is forbidden)
__device__ __align__(16) float g_qkv[(size_t)M_ * QKV_N];   // tf32-rounded q,k
__device__ __align__(16) float g_vt[(size_t)B_ * H_ * D_ * N_]; // tf32-rounded V^T [b,h,d,token]
__device__ __align__(16) float g_ctx[(size_t)M_ * E_];      // tf32-rounded ctx
__device__ __align__(16) float g_x[(size_t)M_ * E_];        // tf32-rounded x
__device__ __align__(16) float g_wqkv[(size_t)QKV_N * E_];  // tf32-rounded w_qkv
__device__ __align__(16) float g_wo[(size_t)E_ * E_];       // tf32-rounded w_o

__device__ __forceinline__ float ex2f(float x) {
    float r;
    asm("ex2.approx.f32 %0, %1;" : "=f"(r) : "f"(x));
    return r;
}
__device__ __forceinline__ uint32_t tf32c(float f) {
    uint32_t u;
    asm("cvt.rna.tf32.f32 %0, %1;" : "=r"(u) : "f"(f));
    return u;
}
__device__ __forceinline__ void mma_tf32(float c[4], const uint32_t a[4],
                                         uint32_t b0, uint32_t b1) {
    asm volatile("mma.sync.aligned.m16n8k8.row.col.f32.tf32.tf32.f32 "
        "{%0,%1,%2,%3}, {%4,%5,%6,%7}, {%8,%9}, {%0,%1,%2,%3};"
        : "+f"(c[0]), "+f"(c[1]), "+f"(c[2]), "+f"(c[3])
        : "r"(a[0]), "r"(a[1]), "r"(a[2]), "r"(a[3]), "r"(b0), "r"(b1));
}
// ldmatrix x4 on tf32 data: each 8x8-tf32 half-tile = one m8n8.b16 tile.
__device__ __forceinline__ void ldsm_x4(uint32_t r[4], uint32_t addr) {
    asm volatile("ldmatrix.sync.aligned.m8n8.x4.shared.b16 {%0,%1,%2,%3}, [%4];"
        : "=r"(r[0]), "=r"(r[1]), "=r"(r[2]), "=r"(r[3]) : "r"(addr));
}
__device__ __forceinline__ void cp16(uint32_t dst, const void* src) {
    asm volatile("cp.async.cg.shared.global [%0], [%1], 16;" :: "r"(dst), "l"(src));
}
__device__ __forceinline__ void cp_commit() {
    asm volatile("cp.async.commit_group;");
}
template <int N>
__device__ __forceinline__ void cp_wait() {
    asm volatile("cp.async.wait_group %0;" :: "n"(N));
}
__device__ __forceinline__ uint32_t smem_u32(const void* p) {
    return (uint32_t)__cvta_generic_to_shared(p);
}

// ---------------------------------------------------------------------------
// Fused pre-round: x, w_qkv, w_o -> tf32-rna-rounded copies (one launch)
// ---------------------------------------------------------------------------
#define NX4  (M_ * E_ / 4)
#define NWQ4 (QKV_N * E_ / 4)
#define NWO4 (E_ * E_ / 4)

__global__ __launch_bounds__(256)
void round_all_kernel(const float* __restrict__ x,
                      const float* __restrict__ wq,
                      const float* __restrict__ wo)
{
    int i = blockIdx.x * 256 + threadIdx.x;
    const float4* src;
    uint4* dst;
    int j;
    if (i < NX4)             { src = (const float4*)x;  dst = (uint4*)g_x;    j = i; }
    else if (i < NX4 + NWQ4) { src = (const float4*)wq; dst = (uint4*)g_wqkv; j = i - NX4; }
    else                     { src = (const float4*)wo; dst = (uint4*)g_wo;   j = i - NX4 - NWQ4; }
    float4 v = src[j];
    dst[j] = make_uint4(tf32c(v.x), tf32c(v.y), tf32c(v.z), tf32c(v.w));
}

// ---------------------------------------------------------------------------
// tf32 MMA GEMM, cp.async 2-stage, ldmatrix fragment feed, 2 CTAs/SM.
// MODE 0: plain fp32 out.  MODE 1: QKV mode — q/k rounded into g_qkv, V
// written tf32-rounded AND transposed into g_vt[b,h,d,token].
// ---------------------------------------------------------------------------
#define GS 36   // smem row stride in floats
#define GT (128 * GS)

template <int MODE>
__global__ __launch_bounds__(256, 2)
void tgemm_kernel(const float* __restrict__ X,
                  const float* __restrict__ W,
                  const float* __restrict__ bias,
                  float* __restrict__ out,
                  int K, int ldOut)
{
    extern __shared__ __align__(16) float smem[];
    // layout: A0 | A1 | B0 | B1, each GT floats

    const int bm = blockIdx.y * 128;
    const int bn = blockIdx.x * 128;
    const int tid = threadIdx.x;
    const int w   = tid >> 5;
    const int L   = tid & 31;
    const int gid = L >> 2;
    const int tig = L & 3;
    const int wm  = (w >> 2) * 64;
    const int wn  = (w & 3) * 32;

    const uint32_t sbase = smem_u32(smem);
    const int lrow = tid >> 3;        // 0..31
    const int lc4  = tid & 7;         // 0..7

    // ldmatrix lane-address offsets (floats)
    const int t4 = L >> 3;            // 0..3
    const int aoff = (wm + (t4 & 1) * 8 + (L & 7)) * GS + (t4 >> 1) * 4;
    const int boff = (wn + (t4 >> 1) * 8 + (L & 7)) * GS + (t4 & 1) * 4;

    float c[4][4][4];
#pragma unroll
    for (int mf = 0; mf < 4; mf++)
#pragma unroll
        for (int nf = 0; nf < 4; nf++)
#pragma unroll
            for (int r = 0; r < 4; r++) c[mf][nf][r] = 0.0f;

    const int nt = K >> 5;            // K / 32

    // prologue: tile 0
#pragma unroll
    for (int i = 0; i < 4; i++) {
        int row = lrow + i * 32;
        cp16(sbase + (uint32_t)(row * GS + lc4 * 4) * 4,
             X + (size_t)(bm + row) * K + lc4 * 4);
        cp16(sbase + (uint32_t)(2 * GT + row * GS + lc4 * 4) * 4,
             W + (size_t)(bn + row) * K + lc4 * 4);
    }
    cp_commit();

    for (int t = 0; t < nt; t++) {
        const int cur = t & 1;
        if (t + 1 < nt) {
            const int nxt = cur ^ 1;
            const int k0 = (t + 1) << 5;
#pragma unroll
            for (int i = 0; i < 4; i++) {
                int row = lrow + i * 32;
                cp16(sbase + (uint32_t)(nxt * GT + row * GS + lc4 * 4) * 4,
                     X + (size_t)(bm + row) * K + k0 + lc4 * 4);
                cp16(sbase + (uint32_t)((2 + nxt) * GT + row * GS + lc4 * 4) * 4,
                     W + (size_t)(bn + row) * K + k0 + lc4 * 4);
            }
            cp_commit();
            cp_wait<1>();
        } else {
            cp_wait<0>();
        }
        __syncthreads();

        const uint32_t uA = sbase + (uint32_t)(cur * GT + aoff) * 4;
        const uint32_t uB = sbase + (uint32_t)((2 + cur) * GT + boff) * 4;

#pragma unroll
        for (int kk = 0; kk < 4; kk++) {
            uint32_t a[4][4];
#pragma unroll
            for (int mf = 0; mf < 4; mf++)
                ldsm_x4(a[mf], uA + (uint32_t)(mf * 16 * GS + kk * 8) * 4);
            uint32_t bf[2][4];
#pragma unroll
            for (int nfp = 0; nfp < 2; nfp++)
                ldsm_x4(bf[nfp], uB + (uint32_t)(nfp * 16 * GS + kk * 8) * 4);
#pragma unroll
            for (int mf = 0; mf < 4; mf++)
#pragma unroll
                for (int nf = 0; nf < 4; nf++)
                    mma_tf32(c[mf][nf], a[mf],
                             bf[nf >> 1][(nf & 1) * 2], bf[nf >> 1][(nf & 1) * 2 + 1]);
        }
        __syncthreads();
    }

    // Epilogue
#pragma unroll
    for (int mf = 0; mf < 4; mf++) {
        int m0 = bm + wm + mf * 16 + gid;
#pragma unroll
        for (int nf = 0; nf < 4; nf++) {
            int n = bn + wn + nf * 8 + tig * 2;
            float b0 = bias[n + 0];
            float b1 = bias[n + 1];
            float v00 = c[mf][nf][0] + b0, v01 = c[mf][nf][1] + b1;
            float v10 = c[mf][nf][2] + b0, v11 = c[mf][nf][3] + b1;
            if (MODE == 1) {
                v00 = __uint_as_float(tf32c(v00));
                v01 = __uint_as_float(tf32c(v01));
                v10 = __uint_as_float(tf32c(v10));
                v11 = __uint_as_float(tf32c(v11));
                int h  = n / 192;
                int rm = n - h * 192;
                if (rm < 128) {
                    *(float2*)(out + (size_t)m0 * ldOut + n) = make_float2(v00, v01);
                    *(float2*)(out + (size_t)(m0 + 8) * ldOut + n) = make_float2(v10, v11);
                } else {
                    // V: write transposed g_vt[b,h,d,token]
                    int dd  = rm - 128;
                    int bbq = m0 >> 11;
                    int tok = m0 & 2047;
                    float* vb = g_vt + ((size_t)(bbq * H_ + h) * D_ + dd) * N_ + tok;
                    vb[0]      = v00;     // (d=dd,   tok)
                    vb[N_]     = v01;     // (d=dd+1, tok)
                    vb[8]      = v10;     // (d=dd,   tok+8)
                    vb[N_ + 8] = v11;     // (d=dd+1, tok+8)
                }
            } else {
                *(float2*)(out + (size_t)m0 * ldOut + n) = make_float2(v00, v01);
                *(float2*)(out + (size_t)(m0 + 8) * ldOut + n) = make_float2(v10, v11);
            }
        }
    }
}

// ---------------------------------------------------------------------------
// Flash attention via tf32 mma.sync, cp.async 2-stage, ldmatrix K and V^T
// fragment feed. P C-frag -> A-frag via per-warp smem buffer (16 STS.64 +
// 8 ldmatrix.x4 per tile) instead of 64 shuffles. 2 CTAs/SM.
// ---------------------------------------------------------------------------
#define KS 68                 // K smem row stride (floats)
#define VS 68                 // V^T smem row stride (floats)
#define KT (64 * KS)          // 4352 floats
#define VT (64 * VS)          // 4352 floats
#define PBASE (2 * KT + 2 * VT)  // 17408 floats
#define PS 68                 // P row stride (floats); 272B: rows walk 16B chunks
#define PWARP (16 * PS)       // 1088 floats per warp
#define ATTN_SMEM ((PBASE + 8 * PWARP) * 4)   // 104448 B
#define NT_ATT (N_ / 64)

__global__ __launch_bounds__(256, 2)
void attn_kernel()
{
    extern __shared__ __align__(16) float smem[];
    // floats: K0 | K1 | V0 | V1 | P(8 warps)

    const int bh  = blockIdx.y;
    const int bb  = bh / H_;
    const int h   = bh - bb * H_;
    const int q0  = blockIdx.x * 128;
    const int tid = threadIdx.x;
    const int w   = tid >> 5;
    const int L   = tid & 31;
    const int gid = L >> 2;
    const int tig = L & 3;

    const size_t qkvbase = (size_t)bb * N_ * QKV_N + (size_t)h * 192;
    const float* vtbase = g_vt + (size_t)(bb * H_ + h) * D_ * N_;
    const float sc = rsqrtf((float)E_) * 1.4426950408889634f;

    const uint32_t sbase = smem_u32(smem);
    const int c4  = tid & 15;             // float4 column for fills
    const int kr0 = tid >> 4;             // 0..15

    // ldmatrix lane-address offsets (floats)
    const int t4 = L >> 3;
    const int koff = ((t4 >> 1) * 8 + (L & 7)) * KS + (t4 & 1) * 4;
    const int voff = ((t4 >> 1) * 8 + (L & 7)) * VS + (t4 & 1) * 4;
    const int pw   = PBASE + w * PWARP;   // this warp's P buffer (floats)
    const int poff = ((t4 & 1) * 8 + (L & 7)) * PS + (t4 >> 1) * 4;
    const uint32_t uP = sbase + (uint32_t)(pw + poff) * 4;

    // ---- Q A-fragments (tf32, pre-scaled) ----
    uint32_t qa[8][4];
    {
        const int m0 = q0 + w * 16 + gid;
        const float* r0p = g_qkv + qkvbase + (size_t)m0 * QKV_N;
        const float* r1p = r0p + (size_t)8 * QKV_N;
#pragma unroll
        for (int kk = 0; kk < 8; kk++) {
            qa[kk][0] = tf32c(r0p[kk * 8 + tig] * sc);
            qa[kk][1] = tf32c(r1p[kk * 8 + tig] * sc);
            qa[kk][2] = tf32c(r0p[kk * 8 + tig + 4] * sc);
            qa[kk][3] = tf32c(r1p[kk * 8 + tig + 4] * sc);
        }
    }

    float o[8][4];
#pragma unroll
    for (int np = 0; np < 8; np++)
#pragma unroll
        for (int r = 0; r < 4; r++) o[np][r] = 0.0f;
    float l0 = 0.0f, l1 = 0.0f;

    // prologue: tile 0.  K rows = keys (from g_qkv +64); V rows = d (from g_vt)
#pragma unroll
    for (int i = 0; i < 4; i++) {
        int r = kr0 + i * 16;
        cp16(sbase + (uint32_t)(r * KS + c4 * 4) * 4,
             g_qkv + qkvbase + (size_t)r * QKV_N + 64 + c4 * 4);
        cp16(sbase + (uint32_t)(2 * KT + r * VS + c4 * 4) * 4,
             vtbase + (size_t)r * N_ + c4 * 4);
    }
    cp_commit();

    for (int t = 0; t < NT_ATT; t++) {
        const int cur = t & 1;
        if (t + 1 < NT_ATT) {
            const int nxt = cur ^ 1;
            const int k0 = (t + 1) * 64;
#pragma unroll
            for (int i = 0; i < 4; i++) {
                int r = kr0 + i * 16;
                cp16(sbase + (uint32_t)(nxt * KT + r * KS + c4 * 4) * 4,
                     g_qkv + qkvbase + (size_t)(k0 + r) * QKV_N + 64 + c4 * 4);
                cp16(sbase + (uint32_t)(2 * KT + nxt * VT + r * VS + c4 * 4) * 4,
                     vtbase + (size_t)r * N_ + k0 + c4 * 4);
            }
            cp_commit();
            cp_wait<1>();
        } else {
            cp_wait<0>();
        }
        __syncthreads();

        const uint32_t uK = sbase + (uint32_t)(cur * KT + koff) * 4;
        const uint32_t uV = sbase + (uint32_t)(2 * KT + cur * VT + voff) * 4;

        // ---- S = Q K^T (tf32) ----
        float s[8][4];
#pragma unroll
        for (int np = 0; np < 8; np++) {
            s[np][0] = 0.f; s[np][1] = 0.f; s[np][2] = 0.f; s[np][3] = 0.f;
        }
#pragma unroll
        for (int kk = 0; kk < 8; kk++) {
#pragma unroll
            for (int npp = 0; npp < 4; npp++) {
                uint32_t kb[4];
                ldsm_x4(kb, uK + (uint32_t)(npp * 16 * KS + kk * 8) * 4);
                mma_tf32(s[2 * npp + 0], qa[kk], kb[0], kb[1]);
                mma_tf32(s[2 * npp + 1], qa[kk], kb[2], kb[3]);
            }
        }

        // ---- softmax (base-2, no max shift) + write P (tf32-rounded) ----
#pragma unroll
        for (int np = 0; np < 8; np++) {
            s[np][0] = ex2f(s[np][0]);
            s[np][1] = ex2f(s[np][1]);
            s[np][2] = ex2f(s[np][2]);
            s[np][3] = ex2f(s[np][3]);
            l0 += s[np][0] + s[np][1];
            l1 += s[np][2] + s[np][3];
            *(uint2*)(smem + pw + gid * PS + np * 8 + tig * 2) =
                make_uint2(tf32c(s[np][0]), tf32c(s[np][1]));
            *(uint2*)(smem + pw + (gid + 8) * PS + np * 8 + tig * 2) =
                make_uint2(tf32c(s[np][2]), tf32c(s[np][3]));
        }
        __syncwarp();

        // ---- O += P V  (P A-frags via ldmatrix; V^T tiles rows = d) ----
#pragma unroll
        for (int kc = 0; kc < 8; kc++) {
            uint32_t pa[4];
            ldsm_x4(pa, uP + (uint32_t)(kc * 8) * 4);
#pragma unroll
            for (int npp = 0; npp < 4; npp++) {
                uint32_t vb[4];
                ldsm_x4(vb, uV + (uint32_t)(npp * 16 * VS + kc * 8) * 4);
                mma_tf32(o[2 * npp + 0], pa, vb[0], vb[1]);
                mma_tf32(o[2 * npp + 1], pa, vb[2], vb[3]);
            }
        }
        __syncthreads();
    }

    // ---- normalize and write ctx (tf32-rounded: feeds tf32 out-proj) ----
    l0 += __shfl_xor_sync(0xffffffff, l0, 1);
    l0 += __shfl_xor_sync(0xffffffff, l0, 2);
    l1 += __shfl_xor_sync(0xffffffff, l1, 1);
    l1 += __shfl_xor_sync(0xffffffff, l1, 2);
    const float inv0 = 1.0f / l0;
    const float inv1 = 1.0f / l1;

    const int m0 = q0 + w * 16 + gid;
    float* d0 = g_ctx + ((size_t)bb * N_ + m0) * E_ + h * D_;
    float* d1 = d0 + (size_t)8 * E_;
#pragma unroll
    for (int np = 0; np < 8; np++) {
        *(uint2*)(d0 + 8 * np + 2 * tig) =
            make_uint2(tf32c(o[np][0] * inv0), tf32c(o[np][1] * inv0));
        *(uint2*)(d1 + 8 * np + 2 * tig) =
            make_uint2(tf32c(o[np][2] * inv1), tf32c(o[np][3] * inv1));
    }
}

// ---------------------------------------------------------------------------
extern "C" void kernel_launch(void* const* d_in, const int* in_sizes, int n_in,
                              void* d_out, int out_size)
{
    const float* x     = (const float*)d_in[0];
    const float* w_qkv = (const float*)d_in[1];
    const float* b_qkv = (const float*)d_in[2];
    const float* w_o   = (const float*)d_in[3];
    const float* b_o   = (const float*)d_in[4];
    float* out = (float*)d_out;

    float *qkv_p, *ctx_p, *x_p, *wqkv_p, *wo_p;
    cudaGetSymbolAddress((void**)&qkv_p, g_qkv);
    cudaGetSymbolAddress((void**)&ctx_p, g_ctx);
    cudaGetSymbolAddress((void**)&x_p, g_x);
    cudaGetSymbolAddress((void**)&wqkv_p, g_wqkv);
    cudaGetSymbolAddress((void**)&wo_p, g_wo);

    static bool attr_done = false;
    const int gemm_smem = 4 * GT * 4;            // 73728 B
    if (!attr_done) {
        cudaFuncSetAttribute(tgemm_kernel<0>,
            cudaFuncAttributeMaxDynamicSharedMemorySize, gemm_smem);
        cudaFuncSetAttribute(tgemm_kernel<1>,
            cudaFuncAttributeMaxDynamicSharedMemorySize, gemm_smem);
        cudaFuncSetAttribute(attn_kernel,
            cudaFuncAttributeMaxDynamicSharedMemorySize, ATTN_SMEM);
        attr_done = true;
    }

    // 0) Pre-round inputs to tf32 (single fused launch)
    round_all_kernel<<<(NX4 + NWQ4 + NWO4) / 256, 256>>>(x, w_qkv, w_o);

    // 1) QKV projection -> g_qkv (q,k) + g_vt (V transposed), tf32-rounded
    tgemm_kernel<1><<<dim3(QKV_N / 128, M_ / 128), 256, gemm_smem>>>(
        x_p, wqkv_p, b_qkv, qkv_p, E_, QKV_N);

    // 2) Attention: g_qkv + g_vt -> g_ctx (tf32-rounded)
    attn_kernel<<<dim3(N_ / 128, B_ * H_), 256, ATTN_SMEM>>>();

    // 3) Output projection -> d_out (full fp32 output)
    tgemm_kernel<0><<<dim3(E_ / 128, M_ / 128), 256, gemm_smem>>>(
        ctx_p, wo_p, b_o, out, E_, E_);
}